// round 8
// baseline (speedup 1.0000x reference)
#include <cuda_runtime.h>
#include <cstdint>

// out[b, i, c] = sum_{j=0..3} x[b, i+j, c] * att[b, i+j]
// x:   [8, 1, 4099, 512] fp32  (evict_last pinned reads, 256-bit LDGs)
// att: [8, 4099] fp32
// out: [8, 1, 4096, 512] fp32  (evict_first streaming stores)

#define SENT_LEN     4096
#define FW           4
#define ROWS_IN      (SENT_LEN + FW - 1)   // 4099
#define CH           512                   // floats per row
#define C8           (CH / 8)              // 64 float8 lanes per row
#define ROWS_PER_BLK 16

__device__ __forceinline__ uint64_t make_evict_last_policy() {
    uint64_t pol;
    asm volatile("createpolicy.fractional.L2::evict_last.b64 %0, 1.0;" : "=l"(pol));
    return pol;
}

// 256-bit global load (8 x fp32), non-coherent, evict_last cache hint.
__device__ __forceinline__ void ld_x8(const float* p, uint64_t pol, float* v) {
    uint32_t u0,u1,u2,u3,u4,u5,u6,u7;
    asm volatile("ld.global.nc.L2::cache_hint.v8.b32 {%0,%1,%2,%3,%4,%5,%6,%7}, [%8], %9;"
                 : "=r"(u0),"=r"(u1),"=r"(u2),"=r"(u3),
                   "=r"(u4),"=r"(u5),"=r"(u6),"=r"(u7)
                 : "l"(p), "l"(pol));
    v[0]=__uint_as_float(u0); v[1]=__uint_as_float(u1);
    v[2]=__uint_as_float(u2); v[3]=__uint_as_float(u3);
    v[4]=__uint_as_float(u4); v[5]=__uint_as_float(u5);
    v[6]=__uint_as_float(u6); v[7]=__uint_as_float(u7);
}

__device__ __forceinline__ float ld_a(const float* p, uint64_t pol) {
    float v;
    asm volatile("ld.global.nc.L2::cache_hint.f32 %0, [%1], %2;"
                 : "=f"(v) : "l"(p), "l"(pol));
    return v;
}

// 8-float streaming store as two STG.128 evict_first.
__device__ __forceinline__ void st_o8(float* p, const float* v) {
    asm volatile("st.global.cs.v4.f32 [%0], {%1,%2,%3,%4};"
                 :: "l"(p), "f"(v[0]), "f"(v[1]), "f"(v[2]), "f"(v[3]) : "memory");
    asm volatile("st.global.cs.v4.f32 [%0], {%1,%2,%3,%4};"
                 :: "l"(p+4), "f"(v[4]), "f"(v[5]), "f"(v[6]), "f"(v[7]) : "memory");
}

__global__ __launch_bounds__(C8)
void wp_slide_kernel(const float* __restrict__ x,
                     const float* __restrict__ att,
                     float* __restrict__ out)
{
    const int lane  = threadIdx.x;           // 0..63 (float8 column lane)
    const int chunk = blockIdx.x;            // 0..255 (row chunk)
    const int b     = blockIdx.y;            // 0..7
    const int i0    = chunk * ROWS_PER_BLK;

    const uint64_t pol = make_evict_last_policy();

    const float* xp = x   + ((long)b * ROWS_IN + i0) * CH + lane * 8;
    float*       op = out + ((long)b * SENT_LEN + i0) * CH + lane * 8;
    const float* ap = att + b * ROWS_IN + i0;

    float a0 = ld_a(ap + 0, pol), a1 = ld_a(ap + 1, pol), a2 = ld_a(ap + 2, pol);

    float w0[8], w1[8], w2[8], t[8];

    ld_x8(xp + 0 * CH, pol, t);
    #pragma unroll
    for (int k = 0; k < 8; ++k) w0[k] = t[k] * a0;
    ld_x8(xp + 1 * CH, pol, t);
    #pragma unroll
    for (int k = 0; k < 8; ++k) w1[k] = t[k] * a1;
    ld_x8(xp + 2 * CH, pol, t);
    #pragma unroll
    for (int k = 0; k < 8; ++k) w2[k] = t[k] * a2;

    #pragma unroll
    for (int r = 0; r < ROWS_PER_BLK; ++r) {
        float a3 = ld_a(ap + r + 3, pol);
        ld_x8(xp + (r + 3) * CH, pol, t);

        float o[8];
        #pragma unroll
        for (int k = 0; k < 8; ++k) {
            float w3 = t[k] * a3;
            o[k] = (w0[k] + w1[k]) + (w2[k] + w3);
            w0[k] = w1[k]; w1[k] = w2[k]; w2[k] = w3;
        }
        st_o8(op + r * CH, o);
    }
}

extern "C" void kernel_launch(void* const* d_in, const int* in_sizes, int n_in,
                              void* d_out, int out_size)
{
    const float* x   = (const float*)d_in[0];
    const float* att = (const float*)d_in[1];
    float*       out = (float*)d_out;

    dim3 grid(SENT_LEN / ROWS_PER_BLK, 8);   // (256, 8) = 2048 blocks
    dim3 block(C8);                          // 64 threads
    wp_slide_kernel<<<grid, block>>>(x, att, out);
}

// round 9
// speedup vs baseline: 1.2884x; 1.2884x over previous
#include <cuda_runtime.h>
#include <cstdint>

// out[b, i, c] = sum_{j=0..3} x[b, i+j, c] * att[b, i+j]
// x:   [8, 1, 4099, 512] fp32 -- read via TMA bulk copy into smem (evict_last)
// att: [8, 4099] fp32         -- broadcast scalar loads
// out: [8, 1, 4096, 512] fp32 -- evict_first streaming stores
//
// Each block: one contiguous 19-row x slab (38,912 B) via cp.async.bulk,
// then sliding-window accumulate from smem. TMA owns read latency hiding.

#define SENT_LEN   4096
#define FW         4
#define ROWS_IN    (SENT_LEN + FW - 1)     // 4099
#define CH         512                      // floats per row
#define C4         (CH / 4)                 // 128 float4 lanes
#define RPB        16                       // output rows per block
#define TILE_ROWS  (RPB + FW - 1)           // 19
#define TILE_BYTES (TILE_ROWS * CH * 4)     // 38912

__global__ __launch_bounds__(C4)
void wp_tma_kernel(const float* __restrict__ x,
                   const float* __restrict__ att,
                   float*       __restrict__ out)
{
    __shared__ __align__(16) float tile[TILE_ROWS * CH];
    __shared__ __align__(8)  uint64_t mbar;

    const int c4    = threadIdx.x;          // 0..127
    const int chunk = blockIdx.x;           // 0..255
    const int b     = blockIdx.y;           // 0..7
    const int i0    = chunk * RPB;

    const float* xsrc = x   + ((long)b * ROWS_IN  + i0) * CH;
    const float* ap   = att +  (long)b * ROWS_IN  + i0;
    float*       op   = out + ((long)b * SENT_LEN + i0) * CH + c4 * 4;

    const uint32_t s_tile = (uint32_t)__cvta_generic_to_shared(tile);
    const uint32_t s_mbar = (uint32_t)__cvta_generic_to_shared(&mbar);

    if (threadIdx.x == 0) {
        asm volatile("mbarrier.init.shared.b64 [%0], %1;"
                     :: "r"(s_mbar), "r"(1) : "memory");
    }
    __syncthreads();

    if (threadIdx.x == 0) {
        uint64_t pol;
        asm volatile("createpolicy.fractional.L2::evict_last.b64 %0, 1.0;" : "=l"(pol));
        asm volatile("mbarrier.arrive.expect_tx.shared.b64 _, [%0], %1;"
                     :: "r"(s_mbar), "r"((uint32_t)TILE_BYTES) : "memory");
        asm volatile("cp.async.bulk.shared::cta.global.mbarrier::complete_tx::bytes.L2::cache_hint"
                     " [%0], [%1], %2, [%3], %4;"
                     :: "r"(s_tile), "l"(xsrc), "r"((uint32_t)TILE_BYTES),
                        "r"(s_mbar), "l"(pol) : "memory");
    }

    // Load attention scalars while the bulk copy is in flight (broadcast, L1-hit cheap).
    float a[TILE_ROWS];
    #pragma unroll
    for (int r = 0; r < TILE_ROWS; ++r) a[r] = __ldg(ap + r);

    // Wait for the tile.
    asm volatile(
        "{\n\t.reg .pred P;\n\t"
        "WAIT_%=:\n\t"
        "mbarrier.try_wait.parity.acquire.cta.shared::cta.b64 P, [%0], %1;\n\t"
        "@!P bra WAIT_%=;\n\t"
        "}" :: "r"(s_mbar), "r"(0) : "memory");

    const float4* trow = reinterpret_cast<const float4*>(tile) + c4;

    float4 v;
    v = trow[0 * C4];
    float4 w0 = make_float4(v.x * a[0], v.y * a[0], v.z * a[0], v.w * a[0]);
    v = trow[1 * C4];
    float4 w1 = make_float4(v.x * a[1], v.y * a[1], v.z * a[1], v.w * a[1]);
    v = trow[2 * C4];
    float4 w2 = make_float4(v.x * a[2], v.y * a[2], v.z * a[2], v.w * a[2]);

    #pragma unroll
    for (int r = 0; r < RPB; ++r) {
        float4 t = trow[(r + 3) * C4];
        float  a3 = a[r + 3];
        float4 o;
        float w3x = t.x * a3, w3y = t.y * a3, w3z = t.z * a3, w3w = t.w * a3;
        o.x = (w0.x + w1.x) + (w2.x + w3x);
        o.y = (w0.y + w1.y) + (w2.y + w3y);
        o.z = (w0.z + w1.z) + (w2.z + w3z);
        o.w = (w0.w + w1.w) + (w2.w + w3w);
        asm volatile("st.global.cs.v4.f32 [%0], {%1,%2,%3,%4};"
                     :: "l"(op + r * CH), "f"(o.x), "f"(o.y), "f"(o.z), "f"(o.w)
                     : "memory");
        w0 = w1; w1 = w2;
        w2 = make_float4(w3x, w3y, w3z, w3w);
    }
}

extern "C" void kernel_launch(void* const* d_in, const int* in_sizes, int n_in,
                              void* d_out, int out_size)
{
    const float* x   = (const float*)d_in[0];
    const float* att = (const float*)d_in[1];
    float*       out = (float*)d_out;

    dim3 grid(SENT_LEN / RPB, 8);   // (256, 8) = 2048 blocks
    dim3 block(C4);                 // 128 threads
    wp_tma_kernel<<<grid, block>>>(x, att, out);
}